// round 13
// baseline (speedup 1.0000x reference)
#include <cuda_runtime.h>
#include <cstdint>

#define Bz 128
#define Sz 512
#define Hz 256
#define Vz 256
#define NCTA 128
#define HSP 264   // hs row pad (floats)

typedef unsigned long long ull;

// h sequence, slab 0 = h0 = zeros (never written). Layout [t][b][j].
__device__ float g_hseq[Sz + 1][Bz][Hz];   // ~67 MB, zero-init at module load
// per-(CTA, local-b-row) flags: g_flag[((bt*8+jt)*8 + lb)*32]
__device__ unsigned g_flag[NCTA * 8 * 32]; // one 128-B L2 line per flag
__device__ unsigned g_done = 0;            // end-of-kernel reset rendezvous

__device__ __forceinline__ void fma2(ull& acc, ull a, ull b) {
    asm("fma.rn.f32x2 %0, %1, %2, %3;" : "=l"(acc) : "l"(a), "l"(b), "l"(acc));
}
__device__ __forceinline__ float f2sum(ull v) {
    return __uint_as_float((unsigned)v) + __uint_as_float((unsigned)(v >> 32));
}
__device__ __forceinline__ float sigmf(float v) { return 1.0f / (1.0f + __expf(-v)); }

__device__ __forceinline__ void st_release_gpu(unsigned* p, unsigned v) {
    asm volatile("st.release.gpu.u32 [%0], %1;" :: "l"(p), "r"(v) : "memory");
}
__device__ __forceinline__ unsigned ld_acquire_gpu(unsigned* p) {
    unsigned v;
    asm volatile("ld.acquire.gpu.u32 %0, [%1];" : "=r"(v) : "l"(p) : "memory");
    return v;
}

// ---- phase-1 dynamic smem layout (offsets in floats) ----
#define OFF_WRZ 0        // float4[128 kp][32 j] = (r_k,r_k1,z_k,z_k1)   64 KB
#define OFF_WN  16384    // float2[128 kp][32 j] = (n_k,n_k1)            32 KB
#define OFF_H   24576    // float [8 b][HSP]  (warp-private blocks)
#define OFF_RED 26688    // float4[2 buf][4 kc][8 b][32 j]               32 KB
#define OFF_WIH 34880    // float4[16 e][32 j]                            8 KB
#define OFF_EMB 36928    // float [256 v][17]                            17 KB
#define OFF_X   41280    // int   [8 b][512 s]                           16 KB
#define SM1_FLOATS 45376 // 181504 bytes

__device__ __forceinline__ float3 compute_gi(const float* sm, int b, int j2,
                                             int t, float3 bih) {
    const int* xs = (const int*)(sm + OFF_X);
    int xv = xs[b * Sz + t];
    float3 acc = bih;
    const float* emb = sm + OFF_EMB;
    const float4* wih = (const float4*)(sm + OFF_WIH);
#pragma unroll
    for (int e = 0; e < 16; ++e) {
        float ev = emb[xv * 17 + e];
        float4 wv = wih[e * 32 + j2];
        acc.x += ev * wv.x; acc.y += ev * wv.y; acc.z += ev * wv.z;
    }
    return acc;
}

// ---------------------------------------------------------------------------
// Phase 1: persistent GRU recurrence. 128 CTAs = 16 b-tiles(8) x 8 j-tiles(32).
// Warp = (b-quad, k-quarter): 2 bq x 4 kq. Reduction depth 4 within a quad
// (named barrier, 128 threads, double-buffered red). hs regions are
// warp-private. Per-row flags: producer warp w releases its row after its own
// STG (+syncwarp); consumer lanes acquire-poll exactly the 2 flags covering
// their slice. ZERO __syncthreads in the steady-state loop.
// ---------------------------------------------------------------------------
__global__ void __launch_bounds__(256, 1)
gru_phase1(const int* __restrict__ x,
           const float* __restrict__ embed,
           const float* __restrict__ W_ih, const float* __restrict__ b_ih,
           const float* __restrict__ W_hh, const float* __restrict__ b_hh)
{
    extern __shared__ float sm[];
    const int tid = threadIdx.x;
    const int jt = blockIdx.x & 7, bt = blockIdx.x >> 3;
    const int j0 = jt * 32, b0 = bt * 8;

    // ---- one-time fills ----
    float4* wrz4 = (float4*)(sm + OFF_WRZ);
    float2* wn2  = (float2*)(sm + OFF_WN);
    for (int i = tid; i < 128 * 32; i += 256) {
        int kp = i >> 5, j2 = i & 31, jg = j0 + j2;
        const float* wr0 = W_hh + (2 * kp) * 768 + jg;
        const float* wr1 = W_hh + (2 * kp + 1) * 768 + jg;
        wrz4[i] = make_float4(wr0[0], wr1[0], wr0[256], wr1[256]);
        wn2[i]  = make_float2(wr0[512], wr1[512]);
    }
    for (int i = tid; i < Vz * 16; i += 256) {
        int v = i >> 4, e = i & 15;
        sm[OFF_EMB + v * 17 + e] = embed[i];
    }
    {
        float4* wih4 = (float4*)(sm + OFF_WIH);
        for (int i = tid; i < 16 * 32; i += 256) {
            int e = i >> 5, j2 = i & 31, jg = j0 + j2;
            wih4[i] = make_float4(W_ih[e * 768 + jg], W_ih[e * 768 + 256 + jg],
                                  W_ih[e * 768 + 512 + jg], 0.f);
        }
    }
    {
        int4* xs4 = (int4*)(sm + OFF_X);
        const int4* xg = (const int4*)x;
        for (int i = tid; i < 1024; i += 256) {
            int bb = i >> 7, s4 = i & 127;
            xs4[i] = xg[(b0 + bb) * 128 + s4];
        }
    }

    const int w  = tid >> 5;           // warp
    const int jl = tid & 31;           // lane
    const int bq = w >> 2;             // b-quad (0/1)
    const int kq = w & 3;              // k-quarter (0..3)

    // finalize identity: warp w handles local b = w, lane = j
    const int jF = j0 + jl;
    float3 bih = make_float3(b_ih[jF], b_ih[256 + jF], b_ih[512 + jF]);
    float3 bhh = make_float3(b_hh[jF], b_hh[256 + jF], b_hh[512 + jF]);
    float hprev = 0.f;                 // h0 = 0, register-carried

    __syncthreads();
    float3 gi = compute_gi(sm, w, jl, 0, bih);

    float*  hs   = sm + OFF_H;
    float4* red4 = (float4*)(sm + OFF_RED);

    // flags
    unsigned* myflag = &g_flag[(((bt * 8 + jt) * 8) + w) * 32];   // row we produce
    // stage mapping: lane -> (row sb, col group sq); two float4s per lane
    const int sb = 4 * bq + (jl >> 3);         // local row staged by this lane
    const int sq = jl & 7;
    const int o1 = 64 * kq + 4 * sq;           // first float4 col offset
    const int o2 = o1 + 32;                    // second
    unsigned* f1 = &g_flag[(((bt * 8 + (2 * kq))     * 8) + sb) * 32];
    unsigned* f2 = &g_flag[(((bt * 8 + (2 * kq + 1)) * 8) + sb) * 32];

    for (int t = 0; t < Sz; ++t) {
        // ---- per-lane acquire-poll of the 2 producers of this lane's slice ----
        if (t > 0) {
            unsigned tgt = (unsigned)t;
            bool ok;
            do {
                bool mine = (ld_acquire_gpu(f1) >= tgt) &
                            (ld_acquire_gpu(f2) >= tgt);
                ok = __all_sync(0xffffffffu, mine);
            } while (!ok);
        }
        // ---- stage warp-private block: rows 4bq..4bq+3, cols [64kq,64kq+64) ----
        {
            const float* hsrc = &g_hseq[t][b0 + sb][0];
            float4 vA = *(const float4*)&hsrc[o1];
            float4 vB = *(const float4*)&hsrc[o2];
            *(float4*)&hs[sb * HSP + o1] = vA;
            *(float4*)&hs[sb * HSP + o2] = vB;
        }
        __syncwarp();

        // ---- kloop: 4 b x 64 k, FFMA2 over k-pairs ----
        ull ar[4], az[4], an[4];
#pragma unroll
        for (int b = 0; b < 4; ++b) { ar[b] = 0ull; az[b] = 0ull; an[b] = 0ull; }
        const int kp0 = 32 * kq;
#pragma unroll
        for (int g4 = 0; g4 < 16; ++g4) {        // 16 groups of 4 k
            const int kb = 64 * kq + g4 * 4;
            ulonglong2 h01[4];
#pragma unroll
            for (int b = 0; b < 4; ++b)
                h01[b] = *(const ulonglong2*)&hs[(4 * bq + b) * HSP + kb];
#pragma unroll
            for (int p = 0; p < 2; ++p) {
                const int kp = kp0 + g4 * 2 + p;
                ulonglong2 wrz = *(const ulonglong2*)&wrz4[kp * 32 + jl];
                ull        wn  = *(const ull*)&wn2[kp * 32 + jl];
#pragma unroll
                for (int b = 0; b < 4; ++b) {
                    ull h = p ? h01[b].y : h01[b].x;
                    fma2(ar[b], h, wrz.x);
                    fma2(az[b], h, wrz.y);
                    fma2(an[b], h, wn);
                }
            }
        }
        // ---- write partials (double-buffered) ----
        {
            const int buf = (t & 1) * 1024;      // float4 units
#pragma unroll
            for (int b = 0; b < 4; ++b)
                red4[buf + (kq * 8 + 4 * bq + b) * 32 + jl] =
                    make_float4(f2sum(ar[b]), f2sum(az[b]), f2sum(an[b]), 0.f);
        }
        // ---- quad-local named barrier (warps 0-3 -> bar 1, 4-7 -> bar 2) ----
        asm volatile("bar.sync %0, %1;" :: "r"(1 + bq), "r"(128) : "memory");

        // ---- finalize: warp w owns local b = w; hprev register-carried ----
        {
            const int buf = (t & 1) * 1024;
            float sr = 0.f, szz = 0.f, sn = 0.f;
#pragma unroll
            for (int kc = 0; kc < 4; ++kc) {
                float4 p = red4[buf + (kc * 8 + w) * 32 + jl];
                sr += p.x; szz += p.y; sn += p.z;
            }
            float r = sigmf(gi.x + sr + bhh.x);
            float z = sigmf(gi.y + szz + bhh.y);
            float n = tanhf(gi.z + r * (sn + bhh.z));
            hprev = (1.0f - z) * n + z * hprev;
            g_hseq[t + 1][b0 + w][jF] = hprev;   // 128 B coalesced per warp
        }
        __syncwarp();                            // warp's STGs ordered

        if (t + 1 < Sz) {
            if (jl == 0) st_release_gpu(myflag, (unsigned)(t + 1));
            gi = compute_gi(sm, w, jl, t + 1, bih);   // hides flag latency
        }
    }

    // reset flags for graph replay: last CTA to finish resets all (every
    // other CTA has passed its final poll before incrementing g_done).
    __threadfence();
    __shared__ unsigned s_d;
    if (tid == 0) s_d = atomicAdd(&g_done, 1u);
    __syncthreads();
    if (s_d == NCTA - 1u) {
        for (int i = tid; i < NCTA * 8; i += 256) g_flag[i * 32] = 0u;
        __syncthreads();
        if (tid == 0) { g_done = 0u; __threadfence(); }
    }
}

// ---------------------------------------------------------------------------
// Phase 2: out[b,t,:] = h_t[b,:] @ W_out + b_out.  (unchanged, measured 326us)
// ---------------------------------------------------------------------------
#define HP 258
#define WP 258
#define SM2_FLOATS (64 * HP + 128 * WP)   // 49536 floats = 198144 B

__global__ void __launch_bounds__(256, 1)
gru_phase2(const float* __restrict__ W_out, const float* __restrict__ b_out,
           float* __restrict__ out)
{
    extern __shared__ float sm2[];
    float* hs  = sm2;              // [64 b][HP]
    float* wsT = sm2 + 64 * HP;    // [128 v][WP]

    const int tid = threadIdx.x;
    const int t  = blockIdx.x;
    const int b0 = blockIdx.y * 64;

    for (int i = tid; i < 64 * 128; i += 256) {
        int bb = i >> 7, c2 = i & 127;
        *(float2*)&hs[bb * HP + c2 * 2] =
            *(const float2*)&g_hseq[t + 1][b0 + bb][c2 * 2];
    }

    const int bi = tid & 15;     // b-tile: 4*bi .. 4*bi+3
    const int vi = tid >> 4;     // v-tile: 8*vi .. 8*vi+7 (within chunk)

    for (int ch = 0; ch < 2; ++ch) {
        if (ch) __syncthreads();
        for (int r = 0; r < 32; ++r) {
            int i = tid + 256 * r;
            int k = i >> 5, c4 = i & 31;
            float4 wv = *(const float4*)&W_out[k * 256 + ch * 128 + c4 * 4];
            wsT[(4 * c4 + 0) * WP + k] = wv.x;
            wsT[(4 * c4 + 1) * WP + k] = wv.y;
            wsT[(4 * c4 + 2) * WP + k] = wv.z;
            wsT[(4 * c4 + 3) * WP + k] = wv.w;
        }
        __syncthreads();

        ull acc[4][8];
#pragma unroll
        for (int ib = 0; ib < 4; ++ib)
#pragma unroll
            for (int iv = 0; iv < 8; ++iv) acc[ib][iv] = 0ull;

        const float* hB = &hs[(4 * bi) * HP];
        const float* wB = &wsT[(8 * vi) * WP];

#pragma unroll 4
        for (int kp = 0; kp < 128; ++kp) {
            ull h0 = *(const ull*)&hB[0 * HP + 2 * kp];
            ull h1 = *(const ull*)&hB[1 * HP + 2 * kp];
            ull h2 = *(const ull*)&hB[2 * HP + 2 * kp];
            ull h3 = *(const ull*)&hB[3 * HP + 2 * kp];
            ull wv[8];
#pragma unroll
            for (int iv = 0; iv < 8; ++iv)
                wv[iv] = *(const ull*)&wB[iv * WP + 2 * kp];
#pragma unroll
            for (int iv = 0; iv < 8; ++iv) {
                fma2(acc[0][iv], h0, wv[iv]);
                fma2(acc[1][iv], h1, wv[iv]);
                fma2(acc[2][iv], h2, wv[iv]);
                fma2(acc[3][iv], h3, wv[iv]);
            }
        }

        int vb = ch * 128 + 8 * vi;
        float4 boA = *(const float4*)&b_out[vb];
        float4 boB = *(const float4*)&b_out[vb + 4];
#pragma unroll
        for (int ib = 0; ib < 4; ++ib) {
            float4 oA, oB;
            oA.x = f2sum(acc[ib][0]) + boA.x;
            oA.y = f2sum(acc[ib][1]) + boA.y;
            oA.z = f2sum(acc[ib][2]) + boA.z;
            oA.w = f2sum(acc[ib][3]) + boA.w;
            oB.x = f2sum(acc[ib][4]) + boB.x;
            oB.y = f2sum(acc[ib][5]) + boB.y;
            oB.z = f2sum(acc[ib][6]) + boB.z;
            oB.w = f2sum(acc[ib][7]) + boB.w;
            size_t obase = (size_t)(b0 + 4 * bi + ib) * (Sz * Vz)
                         + (size_t)t * Vz + vb;
            *(float4*)&out[obase]     = oA;
            *(float4*)&out[obase + 4] = oB;
        }
    }
}

extern "C" void kernel_launch(void* const* d_in, const int* in_sizes, int n_in,
                              void* d_out, int out_size)
{
    const int*   x     = (const int*)  d_in[0];
    const float* embed = (const float*)d_in[1];
    const float* W_ih  = (const float*)d_in[2];
    const float* b_ih  = (const float*)d_in[3];
    const float* W_hh  = (const float*)d_in[4];
    const float* b_hh  = (const float*)d_in[5];
    const float* W_out = (const float*)d_in[6];
    const float* b_out = (const float*)d_in[7];
    float* out = (float*)d_out;

    cudaFuncSetAttribute(gru_phase1, cudaFuncAttributeMaxDynamicSharedMemorySize,
                         SM1_FLOATS * 4);
    cudaFuncSetAttribute(gru_phase2, cudaFuncAttributeMaxDynamicSharedMemorySize,
                         SM2_FLOATS * 4);

    gru_phase1<<<NCTA, 256, SM1_FLOATS * 4>>>(x, embed, W_ih, b_ih, W_hh, b_hh);
    gru_phase2<<<dim3(Sz, 2), 256, SM2_FLOATS * 4>>>(W_out, b_out, out);
}

// round 14
// speedup vs baseline: 1.1622x; 1.1622x over previous
#include <cuda_runtime.h>
#include <cstdint>

#define Bz 128
#define Sz 512
#define Hz 256
#define Vz 256
#define NP1 128          // phase-1 CTAs
#define NWORK 20         // worker CTAs
#define WCUT 520         // workers own tiles tau < WCUT; kernel2 the rest

typedef unsigned long long ull;

// h sequence, slab 0 = h0 = zeros (never written). Layout [t][b][j].
__device__ float g_hseq[Sz + 1][Bz][Hz];   // ~67 MB, zero-init at module load
// one barrier counter per b-tile, padded to its own 128-B L2 line.
// value = 8 * (#steps fully published by that b-tile's 8 CTAs)
__device__ unsigned g_bar[16 * 32];
__device__ unsigned g_done = 0;            // end-of-kernel reset rendezvous (148)

__device__ __forceinline__ void fma2(ull& acc, ull a, ull b) {
    asm("fma.rn.f32x2 %0, %1, %2, %3;" : "=l"(acc) : "l"(a), "l"(b), "l"(acc));
}
__device__ __forceinline__ float f2sum(ull v) {
    return __uint_as_float((unsigned)v) + __uint_as_float((unsigned)(v >> 32));
}
__device__ __forceinline__ float sigmf(float v) { return 1.0f / (1.0f + __expf(-v)); }

__device__ __forceinline__ void red_release_gpu(unsigned* p) {
    asm volatile("red.release.gpu.add.u32 [%0], 1;" :: "l"(p) : "memory");
}
__device__ __forceinline__ unsigned ld_acquire_gpu(unsigned* p) {
    unsigned v;
    asm volatile("ld.acquire.gpu.u32 %0, [%1];" : "=r"(v) : "l"(p) : "memory");
    return v;
}

// ---- phase-1 smem layout (offsets in floats) ----
#define OFF_WRZ 0        // float4[128 kp][32 j]
#define OFF_WN  16384    // float2[128 kp][32 j]
#define OFF_H   24576    // float [8 b][256 k]
#define OFF_RED 26624    // float4[8 kc][8 b][32 j]
#define OFF_WIH 34816    // float4[16 e][32 j]
#define OFF_EMB 36864    // float [256 v][17]
#define OFF_X   41216    // int   [8 b][512 s]
#define SM1_FLOATS 45312

// ---- phase-2 / worker smem layout ----
#define HP 258
#define WP 258
#define SM2_FLOATS (64 * HP + 128 * WP)   // 49536 floats = 198144 B
#define SMEM_BYTES (SM2_FLOATS * 4)       // fused kernel allocates the max

__device__ __forceinline__ float3 compute_gi(const float* sm, int b, int j2,
                                             int t, float3 bih) {
    const int* xs = (const int*)(sm + OFF_X);
    int xv = xs[b * Sz + t];
    float3 acc = bih;
    const float* emb = sm + OFF_EMB;
    const float4* wih = (const float4*)(sm + OFF_WIH);
#pragma unroll
    for (int e = 0; e < 16; ++e) {
        float ev = emb[xv * 17 + e];
        float4 wv = wih[e * 32 + j2];
        acc.x += ev * wv.x; acc.y += ev * wv.y; acc.z += ev * wv.z;
    }
    return acc;
}

// ---------------------------------------------------------------------------
// Phase-2 tile body: out[b0..b0+64, t, :] = h_{t+1} @ W_out + b_out.
// (byte-identical math to the proven 326us phase-2 kernel)
// ---------------------------------------------------------------------------
__device__ void p2_tile(float* sm2, int tid, int t, int b0,
                        const float* __restrict__ W_out,
                        const float* __restrict__ b_out,
                        float* __restrict__ out)
{
    float* hs  = sm2;              // [64 b][HP]
    float* wsT = sm2 + 64 * HP;    // [128 v][WP]

    for (int i = tid; i < 64 * 128; i += 256) {
        int bb = i >> 7, c2 = i & 127;
        *(float2*)&hs[bb * HP + c2 * 2] =
            *(const float2*)&g_hseq[t + 1][b0 + bb][c2 * 2];
    }

    const int bi = tid & 15;
    const int vi = tid >> 4;

    for (int ch = 0; ch < 2; ++ch) {
        if (ch) __syncthreads();
        for (int r = 0; r < 32; ++r) {
            int i = tid + 256 * r;
            int k = i >> 5, c4 = i & 31;
            float4 wv = *(const float4*)&W_out[k * 256 + ch * 128 + c4 * 4];
            wsT[(4 * c4 + 0) * WP + k] = wv.x;
            wsT[(4 * c4 + 1) * WP + k] = wv.y;
            wsT[(4 * c4 + 2) * WP + k] = wv.z;
            wsT[(4 * c4 + 3) * WP + k] = wv.w;
        }
        __syncthreads();

        ull acc[4][8];
#pragma unroll
        for (int ib = 0; ib < 4; ++ib)
#pragma unroll
            for (int iv = 0; iv < 8; ++iv) acc[ib][iv] = 0ull;

        const float* hB = &hs[(4 * bi) * HP];
        const float* wB = &wsT[(8 * vi) * WP];

#pragma unroll 4
        for (int kp = 0; kp < 128; ++kp) {
            ull h0 = *(const ull*)&hB[0 * HP + 2 * kp];
            ull h1 = *(const ull*)&hB[1 * HP + 2 * kp];
            ull h2 = *(const ull*)&hB[2 * HP + 2 * kp];
            ull h3 = *(const ull*)&hB[3 * HP + 2 * kp];
            ull wv[8];
#pragma unroll
            for (int iv = 0; iv < 8; ++iv)
                wv[iv] = *(const ull*)&wB[iv * WP + 2 * kp];
#pragma unroll
            for (int iv = 0; iv < 8; ++iv) {
                fma2(acc[0][iv], h0, wv[iv]);
                fma2(acc[1][iv], h1, wv[iv]);
                fma2(acc[2][iv], h2, wv[iv]);
                fma2(acc[3][iv], h3, wv[iv]);
            }
        }

        int vb = ch * 128 + 8 * vi;
        float4 boA = *(const float4*)&b_out[vb];
        float4 boB = *(const float4*)&b_out[vb + 4];
#pragma unroll
        for (int ib = 0; ib < 4; ++ib) {
            float4 oA, oB;
            oA.x = f2sum(acc[ib][0]) + boA.x;
            oA.y = f2sum(acc[ib][1]) + boA.y;
            oA.z = f2sum(acc[ib][2]) + boA.z;
            oA.w = f2sum(acc[ib][3]) + boA.w;
            oB.x = f2sum(acc[ib][4]) + boB.x;
            oB.y = f2sum(acc[ib][5]) + boB.y;
            oB.z = f2sum(acc[ib][6]) + boB.z;
            oB.w = f2sum(acc[ib][7]) + boB.w;
            size_t obase = (size_t)(b0 + 4 * bi + ib) * (Sz * Vz)
                         + (size_t)t * Vz + vb;
            *(float4*)&out[obase]     = oA;
            *(float4*)&out[obase + 4] = oB;
        }
    }
}

// ---------------------------------------------------------------------------
// Fused kernel, grid = 148 (all co-resident, 1 CTA/SM):
//   bid <  128 : R10 phase-1 recurrence (proven 1401us), arrivals every step.
//   bid >= 128 : phase-2 worker; statically owns tiles tau = widx + 20*i
//                (tau < WCUT), each gated by acquire-polling the 8 b-tile
//                counters for t. Runs on the 20 SMs phase-1 leaves idle.
// ---------------------------------------------------------------------------
__global__ void __launch_bounds__(256, 1)
gru_fused(const int* __restrict__ x,
          const float* __restrict__ embed,
          const float* __restrict__ W_ih, const float* __restrict__ b_ih,
          const float* __restrict__ W_hh, const float* __restrict__ b_hh,
          const float* __restrict__ W_out, const float* __restrict__ b_out,
          float* __restrict__ out)
{
    extern __shared__ float sm[];
    const int tid = threadIdx.x;

    if (blockIdx.x >= NP1) {
        // ================= worker path =================
        const int widx = blockIdx.x - NP1;
        for (int tau = widx; tau < WCUT; tau += NWORK) {
            const int t = tau >> 1, bh = tau & 1;
            // wait until all 8 b-tiles of this half published h_{t+1}
            if (tid < 8) {
                unsigned* f = &g_bar[(bh * 8 + tid) * 32];
                unsigned tgt = 8u * (unsigned)(t + 1);
                while (ld_acquire_gpu(f) < tgt) { }
            }
            __syncthreads();          // also isolates hs reuse across tiles
            p2_tile(sm, tid, t, bh * 64, W_out, b_out, out);
        }
    } else {
        // ================= phase-1 path (R10 verbatim + final arrival) =====
        const int jt = blockIdx.x & 7, bt = blockIdx.x >> 3;
        const int j0 = jt * 32, b0 = bt * 8;

        float4* wrz4 = (float4*)(sm + OFF_WRZ);
        float2* wn2  = (float2*)(sm + OFF_WN);
        for (int i = tid; i < 128 * 32; i += 256) {
            int kp = i >> 5, j2 = i & 31, jg = j0 + j2;
            const float* wr0 = W_hh + (2 * kp) * 768 + jg;
            const float* wr1 = W_hh + (2 * kp + 1) * 768 + jg;
            wrz4[i] = make_float4(wr0[0], wr1[0], wr0[256], wr1[256]);
            wn2[i]  = make_float2(wr0[512], wr1[512]);
        }
        for (int i = tid; i < Vz * 16; i += 256) {
            int v = i >> 4, e = i & 15;
            sm[OFF_EMB + v * 17 + e] = embed[i];
        }
        {
            float4* wih4 = (float4*)(sm + OFF_WIH);
            for (int i = tid; i < 16 * 32; i += 256) {
                int e = i >> 5, j2 = i & 31, jg = j0 + j2;
                wih4[i] = make_float4(W_ih[e * 768 + jg], W_ih[e * 768 + 256 + jg],
                                      W_ih[e * 768 + 512 + jg], 0.f);
            }
        }
        {
            int4* xs4 = (int4*)(sm + OFF_X);
            const int4* xg = (const int4*)x;
            for (int i = tid; i < 1024; i += 256) {
                int bb = i >> 7, s4 = i & 127;
                xs4[i] = xg[(b0 + bb) * 128 + s4];
            }
        }

        const int bF = tid >> 5, j2F = tid & 31, jF = j0 + j2F;
        float3 bih = make_float3(b_ih[jF], b_ih[256 + jF], b_ih[512 + jF]);
        float3 bhh = make_float3(b_hh[jF], b_hh[256 + jF], b_hh[512 + jF]);

        __syncthreads();
        float3 gi = compute_gi(sm, bF, j2F, 0, bih);

        const int w  = tid >> 5;
        const int jl = tid & 31;
        float*  hs   = sm + OFF_H;
        float4* red4 = (float4*)(sm + OFF_RED);
        unsigned* mybar = &g_bar[bt * 32];

        for (int t = 0; t < Sz; ++t) {
            // stage h tile: 8 rows x 256, coalesced
            {
                const float* hsrc = &g_hseq[t][b0 + w][0];
                float4 A = *(const float4*)&hsrc[jl * 4];
                float4 B = *(const float4*)&hsrc[128 + jl * 4];
                *(float4*)&hs[w * 256 + jl * 4]       = A;
                *(float4*)&hs[w * 256 + 128 + jl * 4] = B;
            }
            __syncthreads();

            // kloop: FFMA2 over k-pairs
            ull ar[8], az[8], an[8];
#pragma unroll
            for (int b = 0; b < 8; ++b) { ar[b] = 0ull; az[b] = 0ull; an[b] = 0ull; }
            const int kp0 = w * 16;
#pragma unroll
            for (int q = 0; q < 8; ++q) {
                const int kb = kp0 * 2 + q * 4;
                ulonglong2 h01[8];
#pragma unroll
                for (int b = 0; b < 8; ++b)
                    h01[b] = *(const ulonglong2*)&hs[b * 256 + kb];
#pragma unroll
                for (int p = 0; p < 2; ++p) {
                    const int kp = kp0 + q * 2 + p;
                    ulonglong2 wrz = *(const ulonglong2*)&wrz4[kp * 32 + jl];
                    ull        wn  = *(const ull*)&wn2[kp * 32 + jl];
#pragma unroll
                    for (int b = 0; b < 8; ++b) {
                        ull h = p ? h01[b].y : h01[b].x;
                        fma2(ar[b], h, wrz.x);
                        fma2(az[b], h, wrz.y);
                        fma2(an[b], h, wn);
                    }
                }
            }
#pragma unroll
            for (int b = 0; b < 8; ++b)
                red4[(w * 8 + b) * 32 + jl] =
                    make_float4(f2sum(ar[b]), f2sum(az[b]), f2sum(an[b]), 0.f);
            __syncthreads();

            // finalize gates
            {
                float sr = 0.f, szz = 0.f, sn = 0.f;
#pragma unroll
                for (int kc = 0; kc < 8; ++kc) {
                    float4 p = red4[(kc * 8 + bF) * 32 + j2F];
                    sr += p.x; szz += p.y; sn += p.z;
                }
                float hprev = hs[bF * 256 + jF];
                float r = sigmf(gi.x + sr + bhh.x);
                float z = sigmf(gi.y + szz + bhh.y);
                float n = tanhf(gi.z + r * (sn + bhh.z));
                g_hseq[t + 1][b0 + bF][jF] = (1.0f - z) * n + z * hprev;
            }

            // arrival EVERY step (workers need the final step's flags too)
            __syncthreads();
            if (tid == 0) red_release_gpu(mybar);

            if (t + 1 < Sz) {
                gi = compute_gi(sm, bF, j2F, t + 1, bih);
                if (tid == 0) {
                    unsigned target = (unsigned)(t + 1) * 8u;
                    while (ld_acquire_gpu(mybar) < target) { }
                }
                __syncthreads();
            }
        }
    }

    // reset counters for graph replay: last of ALL 148 CTAs resets.
    __threadfence();
    if (tid == 0) {
        unsigned d = atomicAdd(&g_done, 1u);
        if (d == (NP1 + NWORK) - 1u) {
            for (int i = 0; i < 16; ++i) g_bar[i * 32] = 0u;
            g_done = 0u;
            __threadfence();
        }
    }
}

// ---------------------------------------------------------------------------
// Kernel 2: remaining phase-2 tiles tau in [WCUT, 1024).
// ---------------------------------------------------------------------------
__global__ void __launch_bounds__(256, 1)
gru_tail(const float* __restrict__ W_out, const float* __restrict__ b_out,
         float* __restrict__ out)
{
    extern __shared__ float sm2[];
    const int tau = WCUT + blockIdx.x;
    p2_tile(sm2, threadIdx.x, tau >> 1, (tau & 1) * 64, W_out, b_out, out);
}

extern "C" void kernel_launch(void* const* d_in, const int* in_sizes, int n_in,
                              void* d_out, int out_size)
{
    const int*   x     = (const int*)  d_in[0];
    const float* embed = (const float*)d_in[1];
    const float* W_ih  = (const float*)d_in[2];
    const float* b_ih  = (const float*)d_in[3];
    const float* W_hh  = (const float*)d_in[4];
    const float* b_hh  = (const float*)d_in[5];
    const float* W_out = (const float*)d_in[6];
    const float* b_out = (const float*)d_in[7];
    float* out = (float*)d_out;

    cudaFuncSetAttribute(gru_fused, cudaFuncAttributeMaxDynamicSharedMemorySize,
                         SMEM_BYTES);
    cudaFuncSetAttribute(gru_tail, cudaFuncAttributeMaxDynamicSharedMemorySize,
                         SMEM_BYTES);

    gru_fused<<<NP1 + NWORK, 256, SMEM_BYTES>>>(x, embed, W_ih, b_ih,
                                                W_hh, b_hh, W_out, b_out, out);
    gru_tail<<<1024 - WCUT, 256, SMEM_BYTES>>>(W_out, b_out, out);
}

// round 15
// speedup vs baseline: 1.2573x; 1.0818x over previous
#include <cuda_runtime.h>
#include <cstdint>

#define Bz 128
#define Sz 512
#define Hz 256
#define Vz 256
#define NP1 128          // phase-1 CTAs
#define NWORK 20         // dedicated worker CTAs
#define NTILE 1024       // 512 t x 2 b-halves

typedef unsigned long long ull;

// h sequence, slab 0 = h0 = zeros (never written). Layout [t][b][j].
__device__ float g_hseq[Sz + 1][Bz][Hz];   // ~67 MB, zero-init at module load
// one barrier counter per b-tile, padded to its own 128-B L2 line.
// value = 8 * (#steps fully published by that b-tile's 8 CTAs)
__device__ unsigned g_bar[16 * 32];
__device__ unsigned g_next = 0;            // phase-2 tile work queue
__device__ unsigned g_done = 0;            // end-of-kernel reset rendezvous (148)

__device__ __forceinline__ void fma2(ull& acc, ull a, ull b) {
    asm("fma.rn.f32x2 %0, %1, %2, %3;" : "=l"(acc) : "l"(a), "l"(b), "l"(acc));
}
__device__ __forceinline__ float f2sum(ull v) {
    return __uint_as_float((unsigned)v) + __uint_as_float((unsigned)(v >> 32));
}
__device__ __forceinline__ float sigmf(float v) { return 1.0f / (1.0f + __expf(-v)); }

__device__ __forceinline__ void red_release_gpu(unsigned* p) {
    asm volatile("red.release.gpu.add.u32 [%0], 1;" :: "l"(p) : "memory");
}
__device__ __forceinline__ unsigned ld_acquire_gpu(unsigned* p) {
    unsigned v;
    asm volatile("ld.acquire.gpu.u32 %0, [%1];" : "=r"(v) : "l"(p) : "memory");
    return v;
}

// ---- phase-1 smem layout (offsets in floats) ----
#define OFF_WRZ 0        // float4[128 kp][32 j]
#define OFF_WN  16384    // float2[128 kp][32 j]
#define OFF_H   24576    // float [8 b][256 k]
#define OFF_RED 26624    // float4[8 kc][8 b][32 j]
#define OFF_WIH 34816    // float4[16 e][32 j]
#define OFF_EMB 36864    // float [256 v][17]
#define OFF_X   41216    // int   [8 b][512 s]
#define SM1_FLOATS 45312

// ---- phase-2 tile smem layout ----
#define HP 258
#define WP 258
#define SM2_FLOATS (64 * HP + 128 * WP)   // 49536 floats = 198144 B
#define SMEM_BYTES (SM2_FLOATS * 4)

__device__ __forceinline__ float3 compute_gi(const float* sm, int b, int j2,
                                             int t, float3 bih) {
    const int* xs = (const int*)(sm + OFF_X);
    int xv = xs[b * Sz + t];
    float3 acc = bih;
    const float* emb = sm + OFF_EMB;
    const float4* wih = (const float4*)(sm + OFF_WIH);
#pragma unroll
    for (int e = 0; e < 16; ++e) {
        float ev = emb[xv * 17 + e];
        float4 wv = wih[e * 32 + j2];
        acc.x += ev * wv.x; acc.y += ev * wv.y; acc.z += ev * wv.z;
    }
    return acc;
}

// ---------------------------------------------------------------------------
// Phase-2 tile body (proven): out[b0..b0+64, t, :] = h_{t+1} @ W_out + b_out.
// ---------------------------------------------------------------------------
__device__ void p2_tile(float* sm2, int tid, int t, int b0,
                        const float* __restrict__ W_out,
                        const float* __restrict__ b_out,
                        float* __restrict__ out)
{
    float* hs  = sm2;              // [64 b][HP]
    float* wsT = sm2 + 64 * HP;    // [128 v][WP]

    for (int i = tid; i < 64 * 128; i += 256) {
        int bb = i >> 7, c2 = i & 127;
        *(float2*)&hs[bb * HP + c2 * 2] =
            *(const float2*)&g_hseq[t + 1][b0 + bb][c2 * 2];
    }

    const int bi = tid & 15;
    const int vi = tid >> 4;

    for (int ch = 0; ch < 2; ++ch) {
        if (ch) __syncthreads();
        for (int r = 0; r < 32; ++r) {
            int i = tid + 256 * r;
            int k = i >> 5, c4 = i & 31;
            float4 wv = *(const float4*)&W_out[k * 256 + ch * 128 + c4 * 4];
            wsT[(4 * c4 + 0) * WP + k] = wv.x;
            wsT[(4 * c4 + 1) * WP + k] = wv.y;
            wsT[(4 * c4 + 2) * WP + k] = wv.z;
            wsT[(4 * c4 + 3) * WP + k] = wv.w;
        }
        __syncthreads();

        ull acc[4][8];
#pragma unroll
        for (int ib = 0; ib < 4; ++ib)
#pragma unroll
            for (int iv = 0; iv < 8; ++iv) acc[ib][iv] = 0ull;

        const float* hB = &hs[(4 * bi) * HP];
        const float* wB = &wsT[(8 * vi) * WP];

#pragma unroll 4
        for (int kp = 0; kp < 128; ++kp) {
            ull h0 = *(const ull*)&hB[0 * HP + 2 * kp];
            ull h1 = *(const ull*)&hB[1 * HP + 2 * kp];
            ull h2 = *(const ull*)&hB[2 * HP + 2 * kp];
            ull h3 = *(const ull*)&hB[3 * HP + 2 * kp];
            ull wv[8];
#pragma unroll
            for (int iv = 0; iv < 8; ++iv)
                wv[iv] = *(const ull*)&wB[iv * WP + 2 * kp];
#pragma unroll
            for (int iv = 0; iv < 8; ++iv) {
                fma2(acc[0][iv], h0, wv[iv]);
                fma2(acc[1][iv], h1, wv[iv]);
                fma2(acc[2][iv], h2, wv[iv]);
                fma2(acc[3][iv], h3, wv[iv]);
            }
        }

        int vb = ch * 128 + 8 * vi;
        float4 boA = *(const float4*)&b_out[vb];
        float4 boB = *(const float4*)&b_out[vb + 4];
#pragma unroll
        for (int ib = 0; ib < 4; ++ib) {
            float4 oA, oB;
            oA.x = f2sum(acc[ib][0]) + boA.x;
            oA.y = f2sum(acc[ib][1]) + boA.y;
            oA.z = f2sum(acc[ib][2]) + boA.z;
            oA.w = f2sum(acc[ib][3]) + boA.w;
            oB.x = f2sum(acc[ib][4]) + boB.x;
            oB.y = f2sum(acc[ib][5]) + boB.y;
            oB.z = f2sum(acc[ib][6]) + boB.z;
            oB.w = f2sum(acc[ib][7]) + boB.w;
            size_t obase = (size_t)(b0 + 4 * bi + ib) * (Sz * Vz)
                         + (size_t)t * Vz + vb;
            *(float4*)&out[obase]     = oA;
            *(float4*)&out[obase + 4] = oB;
        }
    }
}

// Pull tiles from the global queue until exhausted. Each tile gate-polls the
// 8 b-tile counters of its b-half (acquire) before reading h.
__device__ void p2_queue_loop(float* sm2, int tid,
                              const float* __restrict__ W_out,
                              const float* __restrict__ b_out,
                              float* __restrict__ out,
                              unsigned* s_tau)
{
    for (;;) {
        if (tid == 0) *s_tau = atomicAdd(&g_next, 1u);
        __syncthreads();               // broadcast tau; isolates smem reuse
        unsigned tau = *s_tau;
        if (tau >= NTILE) break;
        const int t = (int)(tau >> 1), bh = (int)(tau & 1);
        if (tid < 8) {
            unsigned* f = &g_bar[(bh * 8 + tid) * 32];
            unsigned tgt = 8u * (unsigned)(t + 1);
            while (ld_acquire_gpu(f) < tgt) { }
        }
        __syncthreads();
        p2_tile(sm2, tid, t, bh * 64, W_out, b_out, out);
    }
}

// ---------------------------------------------------------------------------
// Fused kernel, grid = 148 (all co-resident, 1 CTA/SM):
//   bid <  128 : R10 phase-1 recurrence, arrival every step; afterwards the
//                CTA joins the phase-2 tile queue.
//   bid >= 128 : phase-2 worker; pulls gated tiles from the queue from t=0.
// ---------------------------------------------------------------------------
__global__ void __launch_bounds__(256, 1)
gru_fused(const int* __restrict__ x,
          const float* __restrict__ embed,
          const float* __restrict__ W_ih, const float* __restrict__ b_ih,
          const float* __restrict__ W_hh, const float* __restrict__ b_hh,
          const float* __restrict__ W_out, const float* __restrict__ b_out,
          float* __restrict__ out)
{
    extern __shared__ float sm[];
    __shared__ unsigned s_tau;
    const int tid = threadIdx.x;

    if (blockIdx.x < NP1) {
        // ================= phase-1 path (R10 verbatim + arrivals) =========
        const int jt = blockIdx.x & 7, bt = blockIdx.x >> 3;
        const int j0 = jt * 32, b0 = bt * 8;

        float4* wrz4 = (float4*)(sm + OFF_WRZ);
        float2* wn2  = (float2*)(sm + OFF_WN);
        for (int i = tid; i < 128 * 32; i += 256) {
            int kp = i >> 5, j2 = i & 31, jg = j0 + j2;
            const float* wr0 = W_hh + (2 * kp) * 768 + jg;
            const float* wr1 = W_hh + (2 * kp + 1) * 768 + jg;
            wrz4[i] = make_float4(wr0[0], wr1[0], wr0[256], wr1[256]);
            wn2[i]  = make_float2(wr0[512], wr1[512]);
        }
        for (int i = tid; i < Vz * 16; i += 256) {
            int v = i >> 4, e = i & 15;
            sm[OFF_EMB + v * 17 + e] = embed[i];
        }
        {
            float4* wih4 = (float4*)(sm + OFF_WIH);
            for (int i = tid; i < 16 * 32; i += 256) {
                int e = i >> 5, j2 = i & 31, jg = j0 + j2;
                wih4[i] = make_float4(W_ih[e * 768 + jg], W_ih[e * 768 + 256 + jg],
                                      W_ih[e * 768 + 512 + jg], 0.f);
            }
        }
        {
            int4* xs4 = (int4*)(sm + OFF_X);
            const int4* xg = (const int4*)x;
            for (int i = tid; i < 1024; i += 256) {
                int bb = i >> 7, s4 = i & 127;
                xs4[i] = xg[(b0 + bb) * 128 + s4];
            }
        }

        const int bF = tid >> 5, j2F = tid & 31, jF = j0 + j2F;
        float3 bih = make_float3(b_ih[jF], b_ih[256 + jF], b_ih[512 + jF]);
        float3 bhh = make_float3(b_hh[jF], b_hh[256 + jF], b_hh[512 + jF]);

        __syncthreads();
        float3 gi = compute_gi(sm, bF, j2F, 0, bih);

        const int w  = tid >> 5;
        const int jl = tid & 31;
        float*  hs   = sm + OFF_H;
        float4* red4 = (float4*)(sm + OFF_RED);
        unsigned* mybar = &g_bar[bt * 32];

        for (int t = 0; t < Sz; ++t) {
            // stage h tile: 8 rows x 256, coalesced
            {
                const float* hsrc = &g_hseq[t][b0 + w][0];
                float4 A = *(const float4*)&hsrc[jl * 4];
                float4 B = *(const float4*)&hsrc[128 + jl * 4];
                *(float4*)&hs[w * 256 + jl * 4]       = A;
                *(float4*)&hs[w * 256 + 128 + jl * 4] = B;
            }
            __syncthreads();

            // kloop: FFMA2 over k-pairs
            ull ar[8], az[8], an[8];
#pragma unroll
            for (int b = 0; b < 8; ++b) { ar[b] = 0ull; az[b] = 0ull; an[b] = 0ull; }
            const int kp0 = w * 16;
#pragma unroll
            for (int q = 0; q < 8; ++q) {
                const int kb = kp0 * 2 + q * 4;
                ulonglong2 h01[8];
#pragma unroll
                for (int b = 0; b < 8; ++b)
                    h01[b] = *(const ulonglong2*)&hs[b * 256 + kb];
#pragma unroll
                for (int p = 0; p < 2; ++p) {
                    const int kp = kp0 + q * 2 + p;
                    ulonglong2 wrz = *(const ulonglong2*)&wrz4[kp * 32 + jl];
                    ull        wn  = *(const ull*)&wn2[kp * 32 + jl];
#pragma unroll
                    for (int b = 0; b < 8; ++b) {
                        ull h = p ? h01[b].y : h01[b].x;
                        fma2(ar[b], h, wrz.x);
                        fma2(az[b], h, wrz.y);
                        fma2(an[b], h, wn);
                    }
                }
            }
#pragma unroll
            for (int b = 0; b < 8; ++b)
                red4[(w * 8 + b) * 32 + jl] =
                    make_float4(f2sum(ar[b]), f2sum(az[b]), f2sum(an[b]), 0.f);
            __syncthreads();

            // finalize gates
            {
                float sr = 0.f, szz = 0.f, sn = 0.f;
#pragma unroll
                for (int kc = 0; kc < 8; ++kc) {
                    float4 p = red4[(kc * 8 + bF) * 32 + j2F];
                    sr += p.x; szz += p.y; sn += p.z;
                }
                float hprev = hs[bF * 256 + jF];
                float r = sigmf(gi.x + sr + bhh.x);
                float z = sigmf(gi.y + szz + bhh.y);
                float n = tanhf(gi.z + r * (sn + bhh.z));
                g_hseq[t + 1][b0 + bF][jF] = (1.0f - z) * n + z * hprev;
            }

            // arrival EVERY step (queue consumers need the final step too)
            __syncthreads();
            if (tid == 0) red_release_gpu(mybar);

            if (t + 1 < Sz) {
                gi = compute_gi(sm, bF, j2F, t + 1, bih);
                if (tid == 0) {
                    unsigned target = (unsigned)(t + 1) * 8u;
                    while (ld_acquire_gpu(mybar) < target) { }
                }
                __syncthreads();
            }
        }
        __syncthreads();
        // recurrence done: join the phase-2 tile queue (reuses smem freely)
        p2_queue_loop(sm, tid, W_out, b_out, out, &s_tau);
    } else {
        // ================= dedicated worker path =================
        p2_queue_loop(sm, tid, W_out, b_out, out, &s_tau);
    }

    // reset counters for graph replay: last of ALL 148 CTAs resets. Every CTA
    // reaches here only after the queue is exhausted, so the reset is safe.
    __threadfence();
    if (tid == 0) {
        unsigned d = atomicAdd(&g_done, 1u);
        if (d == (NP1 + NWORK) - 1u) {
            for (int i = 0; i < 16; ++i) g_bar[i * 32] = 0u;
            g_next = 0u;
            g_done = 0u;
            __threadfence();
        }
    }
}

extern "C" void kernel_launch(void* const* d_in, const int* in_sizes, int n_in,
                              void* d_out, int out_size)
{
    const int*   x     = (const int*)  d_in[0];
    const float* embed = (const float*)d_in[1];
    const float* W_ih  = (const float*)d_in[2];
    const float* b_ih  = (const float*)d_in[3];
    const float* W_hh  = (const float*)d_in[4];
    const float* b_hh  = (const float*)d_in[5];
    const float* W_out = (const float*)d_in[6];
    const float* b_out = (const float*)d_in[7];
    float* out = (float*)d_out;

    cudaFuncSetAttribute(gru_fused, cudaFuncAttributeMaxDynamicSharedMemorySize,
                         SMEM_BYTES);
    gru_fused<<<NP1 + NWORK, 256, SMEM_BYTES>>>(x, embed, W_ih, b_ih,
                                                W_hh, b_hh, W_out, b_out, out);
}